// round 10
// baseline (speedup 1.0000x reference)
#include <cuda_runtime.h>
#include <math.h>

typedef unsigned long long u64;

#define T 256
#define GP 8
#define NB   16
#define NPQ  45
#define NPP  (NPQ*NPQ)
#define NTOT (NB*NPP)
#define NBLK (NTOT/GP)      /* 4050 CTAs */

/* float offsets in dynamic smem */
#define OFF_RS    0         /* 6936  : resized planar [3][8p][289] (17x17)       */
#define OFF_ACT1  6936      /* 24192 : [32ic][9iy][84] (p*9+ix); reused w3/wd/cx */
#define OFF_ACT2  31128     /* 14336 : [64ic][8p][28] (5x5 in 28-stride, pad 0)  */
#define OFF_ACT3  45464     /* 4128  : [8p][516] (px*129+oc)                     */
#define OFF_RAW   49592     /* 1536  : [3][8p][64]                               */
#define OFF_W2S   51128     /* 4096  : w2 tap double buffer                      */
#define OFF_W1    55224     /* 864                                               */
#define OFF_V     56088     /* 512   : [p][64]                                   */
#define OFF_B     56600     /* 288   : b1 b2 b3 bd                               */
#define OFF_CW    56888     /* 128                                               */
#define OFF_VN2   57016     /* 8                                                 */
#define SMEM_FLOATS 57024
#define SMEM_BYTES  (SMEM_FLOATS * 4)

__device__ float    g_ysum[NB * 128];
__device__ unsigned g_count;

/* ---- packed fp32x2 ---- */
__device__ __forceinline__ u64 pack2(float lo, float hi) {
    u64 r; asm("mov.b64 %0, {%1, %2};" : "=l"(r) : "f"(lo), "f"(hi)); return r;
}
__device__ __forceinline__ void unpack2(u64 v, float& lo, float& hi) {
    asm("mov.b64 {%0, %1}, %2;" : "=f"(lo), "=f"(hi) : "l"(v));
}
__device__ __forceinline__ void fma2(u64& d, u64 a, u64 b) {
    asm("fma.rn.f32x2 %0, %1, %2, %0;" : "+l"(d) : "l"(a), "l"(b));
}

__device__ __forceinline__ void cp16(float* dst, const float* src) {
    unsigned s = (unsigned)__cvta_generic_to_shared(dst);
    asm volatile("cp.async.cg.shared.global [%0], [%1], 16;\n" :: "r"(s), "l"(src));
}
__device__ __forceinline__ void cp_commit() { asm volatile("cp.async.commit_group;\n"); }
__device__ __forceinline__ void cp_wait0()  { asm volatile("cp.async.wait_group 0;\n"); }

/* jax.image.resize 'linear' 8->16 */
__device__ __forceinline__ void rtab(int i, int& a0, int& a1, float& w0, float& w1) {
    if (i == 0)       { a0 = 0; a1 = 0; w0 = 1.f;   w1 = 0.f;   }
    else if (i == 15) { a0 = 7; a1 = 7; w0 = 1.f;   w1 = 0.f;   }
    else if (i & 1)   { int m = i >> 1; a0 = m;     a1 = m + 1; w0 = 0.75f; w1 = 0.25f; }
    else              { int m = i >> 1; a0 = m - 1; a1 = m;     w0 = 0.25f; w1 = 0.75f; }
}

__global__ __launch_bounds__(T, 1)
void main_kernel(const float* __restrict__ images,
                 const float* __restrict__ w1, const float* __restrict__ b1,
                 const float* __restrict__ w2, const float* __restrict__ b2,
                 const float* __restrict__ w3, const float* __restrict__ b3,
                 const float* __restrict__ wd, const float* __restrict__ bd,
                 const float* __restrict__ c_x, const float* __restrict__ c_y,
                 const float* __restrict__ comp_w, const float* __restrict__ sigma,
                 float* __restrict__ out)
{
    extern __shared__ float sm[];
    const int tid  = threadIdx.x;
    const int g0   = blockIdx.x * GP;
    const int wid  = tid >> 5;
    const int lane = tid & 31;

    float* s_b  = sm + OFF_B;
    float* s_cw = sm + OFF_CW;

    /* ---- init ---- */
    for (int i = tid; i < 864; i += T) sm[OFF_W1 + i] = w1[i];
    if (tid < 32)  s_b[tid]       = b1[tid];
    if (tid < 64)  s_b[32 + tid]  = b2[tid];
    if (tid < 128) s_b[96 + tid]  = b3[tid];
    if (tid < 64)  s_b[224 + tid] = bd[tid];
    if (tid < 128) s_cw[tid]      = comp_w[tid];
    for (int i = tid; i < OFF_RAW / 4; i += T)          /* zero rs+act1+act2+act3 */
        ((float4*)sm)[i] = make_float4(0.f, 0.f, 0.f, 0.f);

    for (int i = tid; i < 1536; i += T) {
        int c = i >> 9, rem = i & 511, p = rem >> 6, r = rem & 63;
        int iy = r >> 3, ix = r & 7;
        int g = g0 + p, b = g / NPP, pp = g % NPP;
        int py = pp / NPQ, px = pp % NPQ;
        sm[OFF_RAW + i] = images[((b * 96 + py * 2 + iy) * 96 + px * 2 + ix) * 3 + c];
    }
    __syncthreads();

    /* ---- resize 8x8 -> 16x16 into padded 17x17 planes ---- */
    for (int i = tid; i < 6144; i += T) {
        int c = i >> 11, rem = i & 2047, p = rem >> 8, r = rem & 255;
        int oy = r >> 4, ox = r & 15;
        int ay0, ay1, ax0, ax1; float wy0, wy1, wx0, wx1;
        rtab(oy, ay0, ay1, wy0, wy1);
        rtab(ox, ax0, ax1, wx0, wx1);
        const float* rp = sm + OFF_RAW + c * 512 + p * 64;
        float v00 = rp[ay0 * 8 + ax0], v01 = rp[ay0 * 8 + ax1];
        float v10 = rp[ay1 * 8 + ax0], v11 = rp[ay1 * 8 + ax1];
        sm[OFF_RS + c * 2312 + p * 289 + oy * 17 + ox] =
            wy0 * (wx0 * v00 + wx1 * v01) + wy1 * (wx0 * v10 + wx1 * v11);
    }
    __syncthreads();

    /* ---- conv1: M=512 N=32 K=27, TM=8, TN=8; writes act1 [ic][iy*84 + p*9+ix] ---- */
    {
        const int mt = tid >> 2, ng = tid & 3;
        const int p = mt >> 3, oy = mt & 7;
        u64 acc[8][4];
        #pragma unroll
        for (int i = 0; i < 8; i++)
            #pragma unroll
            for (int j = 0; j < 4; j++) acc[i][j] = 0ull;

        #pragma unroll 1
        for (int ky = 0; ky < 3; ky++)
        #pragma unroll 1
        for (int kx = 0; kx < 3; kx++) {
            #pragma unroll
            for (int c = 0; c < 3; c++) {
                const float* ap = sm + OFF_RS + c * 2312 + p * 289 + (2 * oy + ky) * 17 + kx;
                u64 aa[8];
                #pragma unroll
                for (int ox = 0; ox < 8; ox++) { float av = ap[2 * ox]; aa[ox] = pack2(av, av); }
                const u64* wp2 = (const u64*)(sm + OFF_W1 + ((ky * 3 + kx) * 3 + c) * 32 + ng * 8);
                u64 bb[4] = {wp2[0], wp2[1], wp2[2], wp2[3]};
                #pragma unroll
                for (int ox = 0; ox < 8; ox++)
                    #pragma unroll
                    for (int j = 0; j < 4; j++)
                        fma2(acc[ox][j], aa[ox], bb[j]);
            }
        }
        #pragma unroll
        for (int j = 0; j < 4; j++) {
            int oc0 = ng * 8 + 2 * j;
            float bi0 = s_b[oc0], bi1 = s_b[oc0 + 1];
            float* op0 = sm + OFF_ACT1 + oc0 * 756 + oy * 84 + p * 9;
            float* op1 = op0 + 756;
            #pragma unroll
            for (int ox = 0; ox < 8; ox++) {
                float lo, hi; unpack2(acc[ox][j], lo, hi);
                op0[ox] = fmaxf(lo + bi0, 0.f);
                op1[ox] = fmaxf(hi + bi1, 0.f);
            }
        }
    }
    __syncthreads();

    /* ---- conv2: warp = (m-half, oc-quad); lane = (oc-octet, pix) so weight
           LDS carries 2 distinct addresses (full rows, not broadcast) ---- */
    {
        const int mh  = wid >> 2;          /* p-half: p in {mh*4 .. mh*4+3} */
        const int ocq = wid & 3;
        const int ocg = lane & 1;
        const int pix = lane >> 1;         /* 16: (oy, ox) */
        const int oy = pix >> 2, ox = pix & 3;
        const int oc0 = ocq * 16 + ocg * 8;
        u64 acc[4][4];
        #pragma unroll
        for (int i = 0; i < 4; i++)
            #pragma unroll
            for (int j = 0; j < 4; j++) acc[i][j] = 0ull;

        #pragma unroll
        for (int j = 0; j < 2; j++) {
            int i4 = tid + j * 256;
            cp16(sm + OFF_W2S + i4 * 4, w2 + i4 * 4);
        }
        cp_commit();

        #pragma unroll 1
        for (int t = 0; t < 9; t++) {
            cp_wait0();
            __syncthreads();
            if (t < 8) {
                #pragma unroll
                for (int j = 0; j < 2; j++) {
                    int i4 = tid + j * 256;
                    cp16(sm + OFF_W2S + ((t + 1) & 1) * 2048 + i4 * 4,
                         w2 + (t + 1) * 2048 + i4 * 4);
                }
                cp_commit();
            }
            int ky = t / 3, kx = t - ky * 3;
            const float* ab = sm + OFF_ACT1 + (2 * oy + ky) * 84 + (mh * 4) * 9 + (2 * ox + kx);
            const float* wb = sm + OFF_W2S + (t & 1) * 2048 + oc0;
            #pragma unroll 8
            for (int ic = 0; ic < 32; ic++) {
                ulonglong2 wA = *(const ulonglong2*)(wb + ic * 64);       /* 2 distinct/instr */
                ulonglong2 wB = *(const ulonglong2*)(wb + ic * 64 + 4);
                const float* ai = ab + ic * 756;
                #pragma unroll
                for (int i = 0; i < 4; i++) {
                    float av = ai[9 * i];
                    u64 aa = pack2(av, av);
                    fma2(acc[i][0], aa, wA.x);
                    fma2(acc[i][1], aa, wA.y);
                    fma2(acc[i][2], aa, wB.x);
                    fma2(acc[i][3], aa, wB.y);
                }
            }
        }
        #pragma unroll
        for (int j = 0; j < 4; j++) {
            int oc = oc0 + 2 * j;
            float bi0 = s_b[32 + oc], bi1 = s_b[32 + oc + 1];
            #pragma unroll
            for (int i = 0; i < 4; i++) {
                int p = mh * 4 + i;
                float lo, hi; unpack2(acc[i][j], lo, hi);
                float* o = sm + OFF_ACT2 + oc * 224 + p * 28 + oy * 5 + ox;
                o[0]   = fmaxf(lo + bi0, 0.f);
                o[224] = fmaxf(hi + bi1, 0.f);
            }
        }
    }
    __syncthreads();

    /* ---- conv3: warp = 16 oc; lane = (m-pair, oc-octet), 2-addr weight loads ---- */
    {
        const int oc0 = wid * 16;
        const int ocg = lane & 1;
        const int mgp = lane >> 1;
        const int p   = mgp >> 1;
        const int pxh = mgp & 1;
        u64 acc[2][4];
        #pragma unroll
        for (int i = 0; i < 2; i++)
            #pragma unroll
            for (int j = 0; j < 4; j++) acc[i][j] = 0ull;

        #pragma unroll
        for (int j = 0; j < 8; j++) {
            int i4 = tid + j * 256;
            cp16(sm + OFF_ACT1 + i4 * 4, w3 + i4 * 4);
        }
        cp_commit();

        #pragma unroll 1
        for (int t = 0; t < 9; t++) {
            cp_wait0();
            __syncthreads();
            if (t < 8) {
                #pragma unroll
                for (int j = 0; j < 8; j++) {
                    int i4 = tid + j * 256;
                    cp16(sm + OFF_ACT1 + ((t + 1) & 1) * 8192 + i4 * 4,
                         w3 + (t + 1) * 8192 + i4 * 4);
                }
                cp_commit();
            }
            int ky = t / 3, kx = t - (t / 3) * 3;
            const int iy = 2 * pxh + ky;
            if (iy < 4) {
                const float* wb = sm + OFF_ACT1 + (t & 1) * 8192 + oc0 + ocg * 8;
                const float* ap = sm + OFF_ACT2 + p * 28 + iy * 5 + kx;
                #pragma unroll 4
                for (int ic = 0; ic < 64; ic++) {
                    ulonglong2 wA = *(const ulonglong2*)(wb + ic * 128);
                    ulonglong2 wB = *(const ulonglong2*)(wb + ic * 128 + 4);
                    float a0 = ap[ic * 224];
                    u64 aa0 = pack2(a0, a0);
                    fma2(acc[0][0], aa0, wA.x); fma2(acc[0][1], aa0, wA.y);
                    fma2(acc[0][2], aa0, wB.x); fma2(acc[0][3], aa0, wB.y);
                    if (kx < 2) {
                        float a1 = ap[ic * 224 + 2];
                        u64 aa1 = pack2(a1, a1);
                        fma2(acc[1][0], aa1, wA.x); fma2(acc[1][1], aa1, wA.y);
                        fma2(acc[1][2], aa1, wB.x); fma2(acc[1][3], aa1, wB.y);
                    }
                }
            }
        }
        #pragma unroll
        for (int i = 0; i < 2; i++) {
            int px = 2 * pxh + i;
            #pragma unroll
            for (int j = 0; j < 4; j++) {
                int oc = oc0 + ocg * 8 + 2 * j;
                float lo, hi; unpack2(acc[i][j], lo, hi);
                float* o = sm + OFF_ACT3 + p * 516 + px * 129 + oc;
                o[0] = fmaxf(lo + s_b[96 + oc], 0.f);
                o[1] = fmaxf(hi + s_b[96 + oc + 1], 0.f);
            }
        }
    }
    __syncthreads();

    /* ---- dense 512->64: warp=oc-group(8), lanes=(kq,p); butterfly K-reduce ---- */
    {
        const int oc0 = wid * 8;
        const int kq = lane >> 3, pl = lane & 7;
        u64 acc[4] = {0ull, 0ull, 0ull, 0ull};

        #pragma unroll 1
        for (int s = 0; s < 2; s++) {
            __syncthreads();
            #pragma unroll
            for (int j = 0; j < 16; j++) {
                int idx = tid + j * 256;
                int row = idx >> 4;
                int col = (idx & 15) * 4;
                int kqs = row >> 6, rr = row & 63;
                cp16(sm + OFF_ACT1 + kqs * 4104 + rr * 64 + col,
                     wd + (kqs * 128 + s * 64 + rr) * 64 + col);
            }
            cp_commit();
            cp_wait0();
            __syncthreads();

            const float* xp = sm + OFF_ACT3 + pl * 516 + kq * 129 + s * 64;
            const float* wp = sm + OFF_ACT1 + kq * 4104 + oc0;
            #pragma unroll 8
            for (int kk = 0; kk < 64; kk++) {
                float x = xp[kk];
                u64 xx = pack2(x, x);
                ulonglong2 w01 = *(const ulonglong2*)(wp + kk * 64);
                ulonglong2 w23 = *(const ulonglong2*)(wp + kk * 64 + 4);
                fma2(acc[0], xx, w01.x); fma2(acc[1], xx, w01.y);
                fma2(acc[2], xx, w23.x); fma2(acc[3], xx, w23.y);
            }
        }
        float r[8];
        #pragma unroll
        for (int j = 0; j < 4; j++) unpack2(acc[j], r[2 * j], r[2 * j + 1]);
        #pragma unroll
        for (int j = 0; j < 8; j++) {
            r[j] += __shfl_xor_sync(0xffffffffu, r[j], 8);
            r[j] += __shfl_xor_sync(0xffffffffu, r[j], 16);
        }
        if (kq == 0) {
            #pragma unroll
            for (int j = 0; j < 8; j++) {
                int e = oc0 + j;
                sm[OFF_V + pl * 64 + e] = r[j] + s_b[224 + e];
            }
        }
    }
    __syncthreads();

    /* ---- head: vn2, stage c_x (stride 65), d2 -> ow -> atomics ---- */
    if (tid < GP) {
        float a = 0.f;
        const float* vp = sm + OFF_V + tid * 64;
        #pragma unroll 8
        for (int e = 0; e < 64; e++) a = fmaf(vp[e], vp[e], a);
        sm[OFF_VN2 + tid] = a;
    }
    for (int i = tid; i < 8192; i += T) {
        int k = i >> 6, e = i & 63;
        sm[OFF_ACT1 + k * 65 + e] = c_x[i];
    }
    __syncthreads();

    {
        float inv_s2 = 1.f / (sigma[0] * sigma[0]);
        int k = tid & 127, pg = tid >> 7;
        u64 d01 = pack2(sm[OFF_VN2 + pg * 4],     sm[OFF_VN2 + pg * 4 + 1]);
        u64 d23 = pack2(sm[OFF_VN2 + pg * 4 + 2], sm[OFF_VN2 + pg * 4 + 3]);
        const u64 neg2 = pack2(-2.f, -2.f);
        const float* vp = sm + OFF_V + pg * 256;
        const float* ck = sm + OFF_ACT1 + k * 65;
        #pragma unroll 8
        for (int e = 0; e < 64; e++) {
            float cv = ck[e];
            u64 cc = pack2(cv, cv);
            u64 v01 = pack2(vp[e],       vp[64 + e]);
            u64 v23 = pack2(vp[128 + e], vp[192 + e]);
            u64 t01 = cc, t23 = cc;
            fma2(t01, neg2, v01);
            fma2(t23, neg2, v23);
            fma2(d01, cc, t01);
            fma2(d23, cc, t23);
        }
        float d[4];
        unpack2(d01, d[0], d[1]);
        unpack2(d23, d[2], d[3]);
        int b0 = (g0 + pg * 4)     / NPP;
        int b3 = (g0 + pg * 4 + 3) / NPP;
        float accA = 0.f, accB = 0.f;
        float cwk = s_cw[k];
        #pragma unroll
        for (int pp = 0; pp < 4; pp++) {
            float dd = fmaxf(d[pp], 0.f);
            float owv = fmaxf(cwk * expf(-dd * inv_s2), 1e-10f);
            int b = (g0 + pg * 4 + pp) / NPP;
            if (b == b0) accA += owv; else accB += owv;
        }
        atomicAdd(&g_ysum[b0 * 128 + k], accA);
        if (b3 != b0) atomicAdd(&g_ysum[b3 * 128 + k], accB);
    }

    /* ---- last-CTA finalize ---- */
    __syncthreads();
    __shared__ unsigned s_rank;
    if (tid == 0) {
        __threadfence();
        s_rank = atomicAdd(&g_count, 1u);
    }
    __syncthreads();
    if (s_rank == NBLK - 1) {
        __threadfence();
        float* s_y   = sm + OFF_RS;
        float* yv2   = s_y + 2048;
        float* rsum  = yv2 + 1280;
        for (int i = tid; i < NB * 128; i += T) {
            s_y[i] = g_ysum[i];
            g_ysum[i] = 0.f;
        }
        if (tid == 0) g_count = 0u;
        __syncthreads();
        for (int k = tid; k < 128; k += T) {
            float n2 = 0.f;
            #pragma unroll
            for (int i = 0; i < 10; i++) { float c = c_y[k * 10 + i]; n2 = fmaf(c, c, n2); }
            float inv = 1.f / n2;
            #pragma unroll
            for (int i = 0; i < 10; i++) { float c = c_y[k * 10 + i]; yv2[k * 10 + i] = c * c * inv; }
        }
        if (tid < NB) {
            float s = 0.f;
            for (int k = 0; k < 128; k++) s += s_y[tid * 128 + k];
            rsum[tid] = s;
        }
        __syncthreads();
        if (tid < NB * 10) {
            int b = tid / 10, i = tid % 10;
            float a = 0.f;
            for (int k = 0; k < 128; k++) a = fmaf(s_y[b * 128 + k], yv2[k * 10 + i], a);
            out[tid] = a / rsum[b];
        }
    }
}

extern "C" void kernel_launch(void* const* d_in, const int* in_sizes, int n_in,
                              void* d_out, int out_size) {
    (void)in_sizes; (void)n_in; (void)out_size;
    const float* images = (const float*)d_in[0];
    const float* w1     = (const float*)d_in[1];
    const float* b1     = (const float*)d_in[2];
    const float* w2     = (const float*)d_in[3];
    const float* b2     = (const float*)d_in[4];
    const float* w3     = (const float*)d_in[5];
    const float* b3     = (const float*)d_in[6];
    const float* wd     = (const float*)d_in[7];
    const float* bd     = (const float*)d_in[8];
    const float* c_x    = (const float*)d_in[9];
    const float* c_y    = (const float*)d_in[10];
    const float* comp_w = (const float*)d_in[11];
    const float* sigma  = (const float*)d_in[12];
    float* out = (float*)d_out;

    cudaFuncSetAttribute(main_kernel, cudaFuncAttributeMaxDynamicSharedMemorySize, SMEM_BYTES);

    main_kernel<<<NBLK, T, SMEM_BYTES>>>(images, w1, b1, w2, b2, w3, b3,
                                         wd, bd, c_x, c_y, comp_w, sigma, out);
}